// round 7
// baseline (speedup 1.0000x reference)
#include <cuda_runtime.h>
#include <cuda_bf16.h>
#include <cstdint>
#include <cstddef>

// ---------------------------------------------------------------------------
// out[s,o] = sum_r lambda[s,r] * sigmoid( X[s,:] . W[r*512+o,:] + b[r*512+o] )
// S=8192, K=1024, R=16, O=512.
//
// compute_103 (no 'a') PTX target => no tcgen05. Use classic bf16 HMMA
// (mma.sync.m16n8k16) with cp.async pipeline, fused sigmoid/lambda epilogue.
//
//  pack_kernel: fp32 -> bf16 row-major copies of X and W in device scratch.
//  somfnn_main: grid 256 = 64 S-tiles(128) x 4 O-tiles(128). Per CTA loop
//    it=0..255 (rule = it>>4, kchunk = it&15, BK=64):
//      4-stage cp.async pipeline (A tile 16KB + B tile 16KB per stage),
//      8 warps x (64x32) warp tiles, m16n8k16 fragments via ldmatrix.
//    After each rule: acc -> sigmoid -> out_acc += lambda*sig (regs), acc=0.
//    Final: coalesced float2 stores of the 128x128 out tile.
// ---------------------------------------------------------------------------

#define BM 128
#define BN 128
#define BK 64
#define STAGES 4
#define A_BYTES (BM * BK * 2)             // 16384
#define B_BYTES (BN * BK * 2)             // 16384
#define STAGE_BYTES (A_BYTES + B_BYTES)   // 32768
#define SMEM_BYTES (STAGES * STAGE_BYTES) // 131072
#define NITER 256

__device__ __align__(16) __nv_bfloat16 gXbf[8388608];   // 8192 x 1024
__device__ __align__(16) __nv_bfloat16 gWbf[8388608];   // 8192 x 1024

// ------------------------------ PTX helpers --------------------------------
static __device__ __forceinline__ uint32_t smem_u32(const void* p) {
    uint32_t a;
    asm("{ .reg .u64 t; cvta.to.shared.u64 t, %1; cvt.u32.u64 %0, t; }"
        : "=r"(a) : "l"(p));
    return a;
}
static __device__ __forceinline__ void cpa16(uint32_t dst, const void* src) {
    asm volatile("cp.async.cg.shared.global [%0], [%1], 16;"
                 :: "r"(dst), "l"(src) : "memory");
}
static __device__ __forceinline__ void cp_commit() {
    asm volatile("cp.async.commit_group;" ::: "memory");
}
template <int N> static __device__ __forceinline__ void cp_wait() {
    asm volatile("cp.async.wait_group %0;" :: "n"(N) : "memory");
}
static __device__ __forceinline__ void ldsm4(uint32_t& r0, uint32_t& r1,
                                             uint32_t& r2, uint32_t& r3,
                                             uint32_t addr) {
    asm volatile("ldmatrix.sync.aligned.m8n8.x4.shared.b16 {%0,%1,%2,%3}, [%4];"
                 : "=r"(r0), "=r"(r1), "=r"(r2), "=r"(r3) : "r"(addr));
}
static __device__ __forceinline__ void mma16816(
    float& c0, float& c1, float& c2, float& c3,
    uint32_t a0, uint32_t a1, uint32_t a2, uint32_t a3,
    uint32_t b0, uint32_t b1) {
    asm volatile(
        "mma.sync.aligned.m16n8k16.row.col.f32.bf16.bf16.f32 "
        "{%0,%1,%2,%3}, {%4,%5,%6,%7}, {%8,%9}, {%0,%1,%2,%3};"
        : "+f"(c0), "+f"(c1), "+f"(c2), "+f"(c3)
        : "r"(a0), "r"(a1), "r"(a2), "r"(a3), "r"(b0), "r"(b1));
}

// --------------------------- fp32 -> bf16 pack -----------------------------
__global__ void pack_kernel(const float* __restrict__ X,
                            const float* __restrict__ W) {
    unsigned q = blockIdx.x * blockDim.x + threadIdx.x;  // 2^21 threads exactly
    const float4* src;
    uint4* dst;
    if (q < (1u << 20)) {
        src = reinterpret_cast<const float4*>(X) + (size_t)q * 2;
        dst = reinterpret_cast<uint4*>(gXbf) + q;
    } else {
        unsigned p = q - (1u << 20);
        src = reinterpret_cast<const float4*>(W) + (size_t)p * 2;
        dst = reinterpret_cast<uint4*>(gWbf) + p;
    }
    float4 v0 = src[0];
    float4 v1 = src[1];
    __nv_bfloat162 b0 = __floats2bfloat162_rn(v0.x, v0.y);
    __nv_bfloat162 b1 = __floats2bfloat162_rn(v0.z, v0.w);
    __nv_bfloat162 b2 = __floats2bfloat162_rn(v1.x, v1.y);
    __nv_bfloat162 b3 = __floats2bfloat162_rn(v1.z, v1.w);
    uint4 o;
    o.x = *reinterpret_cast<unsigned*>(&b0);
    o.y = *reinterpret_cast<unsigned*>(&b1);
    o.z = *reinterpret_cast<unsigned*>(&b2);
    o.w = *reinterpret_cast<unsigned*>(&b3);
    *dst = o;
}

// ------------------------------- main kernel -------------------------------
__global__ void __launch_bounds__(256, 1) somfnn_main(
    const float* __restrict__ bias,      // [8192] = [16 rules x 512]
    const float* __restrict__ lambdas,   // [8192 x 16]
    float* __restrict__ out)             // [8192 x 512]
{
    extern __shared__ __align__(128) unsigned char smem[];
    const uint32_t sb = smem_u32(smem);

    const int tid  = threadIdx.x;
    const int lane = tid & 31;
    const int wid  = tid >> 5;
    const int st   = blockIdx.x >> 2;    // S-tile 0..63
    const int ot   = blockIdx.x & 3;     // O-tile 0..3
    const int wm   = wid >> 2;           // 0..1 -> rows wm*64
    const int wn   = wid & 3;            // 0..3 -> cols wn*32

    // ---- loader mapping: thread t loads row t/2, 4 x 16B chunks ----
    const int ldrow = tid >> 1;                 // 0..127
    const int ldc0  = (tid & 1) * 4;            // chunk base 0 or 4 (of 8)
    const uint32_t swz = (uint32_t)(ldrow & 7);
    const __nv_bfloat16* aG = gXbf + (size_t)(st * 128 + ldrow) * 1024;
    const __nv_bfloat16* bG = gWbf + (size_t)(ot * 128 + ldrow) * 1024;
    const uint32_t aDst = sb + (uint32_t)ldrow * 128;
    const uint32_t bDst = sb + A_BYTES + (uint32_t)ldrow * 128;

    auto load_stage = [&](int itL) {
        const int s    = itL & 3;
        const int rule = itL >> 4;
        const int kt   = itL & 15;
        const __nv_bfloat16* as = aG + kt * 64 + ldc0 * 8;
        const __nv_bfloat16* bs = bG + (size_t)rule * 524288 + kt * 64 + ldc0 * 8;
        const uint32_t ab = aDst + (uint32_t)s * STAGE_BYTES;
        const uint32_t bb = bDst + (uint32_t)s * STAGE_BYTES;
#pragma unroll
        for (int j = 0; j < 4; j++) {
            const uint32_t off = (((uint32_t)(ldc0 + j) ^ swz) * 16u);
            cpa16(ab + off, as + j * 8);
            cpa16(bb + off, bs + j * 8);
        }
    };

    // ---- ldmatrix per-lane invariants ----
    const int laneLo = lane & 15;
    const int laneHi = lane >> 4;
    // A frag (mi, ks): row = wm*64 + mi*16 + laneLo, chunk = ks*2 + laneHi
    const uint32_t aRowOff = (uint32_t)(wm * 64 + laneLo) * 128;
    const uint32_t sA      = (uint32_t)((wm * 64 + laneLo) & 7);
    // B x4 (nh, ks): row = wn*32 + nh*16 + (lane>>4)*8 + (lane&7)
    //               chunk = ks*2 + ((lane>>3)&1)
    const uint32_t bRowOff  = (uint32_t)(wn * 32 + ((lane >> 4) << 3) + (lane & 7)) * 128;
    const uint32_t sB       = (uint32_t)(lane & 7);
    const uint32_t bChunkLo = (uint32_t)((lane >> 3) & 1);

    float acc[4][4][4];   // MMA accumulators (current rule)
    float oac[4][4][4];   // lambda-weighted output accumulators
#pragma unroll
    for (int mi = 0; mi < 4; mi++)
#pragma unroll
        for (int nj = 0; nj < 4; nj++)
#pragma unroll
            for (int q = 0; q < 4; q++) { acc[mi][nj][q] = 0.f; oac[mi][nj][q] = 0.f; }

    const int rowL = lane >> 2;         // 0..7
    const int colL = 2 * (lane & 3);    // 0,2,4,6

    // ---- prologue: fill 3 stages ----
    load_stage(0); cp_commit();
    load_stage(1); cp_commit();
    load_stage(2); cp_commit();

#pragma unroll 1
    for (int it = 0; it < NITER; it++) {
        __syncthreads();                 // all warps done reading stage (it+3)&3
        if (it + 3 < NITER) load_stage(it + 3);
        cp_commit();
        cp_wait<3>();                    // stage it&3 data arrived (this thread)
        __syncthreads();                 // ... and visible to all warps

        const uint32_t As = sb + (uint32_t)(it & 3) * STAGE_BYTES;
        const uint32_t Bs = As + A_BYTES;

#pragma unroll
        for (int ks = 0; ks < 4; ks++) {
            uint32_t a[4][4];
#pragma unroll
            for (int mi = 0; mi < 4; mi++) {
                const uint32_t addr = As + aRowOff + (uint32_t)(mi * 16 * 128)
                                    + (((uint32_t)(ks * 2 + laneHi) ^ sA) * 16u);
                ldsm4(a[mi][0], a[mi][1], a[mi][2], a[mi][3], addr);
            }
            uint32_t b[4][2];
#pragma unroll
            for (int nh = 0; nh < 2; nh++) {
                const uint32_t addr = Bs + bRowOff + (uint32_t)(nh * 16 * 128)
                                    + ((((uint32_t)(ks * 2) + bChunkLo) ^ sB) * 16u);
                uint32_t r0, r1, r2, r3;
                ldsm4(r0, r1, r2, r3, addr);
                b[nh * 2][0] = r0; b[nh * 2][1] = r1;
                b[nh * 2 + 1][0] = r2; b[nh * 2 + 1][1] = r3;
            }
#pragma unroll
            for (int mi = 0; mi < 4; mi++)
#pragma unroll
                for (int nj = 0; nj < 4; nj++)
                    mma16816(acc[mi][nj][0], acc[mi][nj][1],
                             acc[mi][nj][2], acc[mi][nj][3],
                             a[mi][0], a[mi][1], a[mi][2], a[mi][3],
                             b[nj][0], b[nj][1]);
        }

        // ---- per-rule epilogue: sigmoid + lambda-weighted accumulate ----
        if ((it & 15) == 15) {
            const int r = it >> 4;
#pragma unroll
            for (int mi = 0; mi < 4; mi++) {
                const int r0g = st * 128 + wm * 64 + mi * 16 + rowL;
                const float l0 = __ldg(lambdas + (size_t)r0g * 16 + r);
                const float l1 = __ldg(lambdas + (size_t)(r0g + 8) * 16 + r);
#pragma unroll
                for (int nj = 0; nj < 4; nj++) {
                    const int col = ot * 128 + wn * 32 + nj * 8 + colL;
                    const float2 bb = *reinterpret_cast<const float2*>(
                        bias + r * 512 + col);
                    float z0 = acc[mi][nj][0] + bb.x;
                    float z1 = acc[mi][nj][1] + bb.y;
                    float z2 = acc[mi][nj][2] + bb.x;
                    float z3 = acc[mi][nj][3] + bb.y;
                    float s0 = __fdividef(1.f, 1.f + __expf(-z0));
                    float s1 = __fdividef(1.f, 1.f + __expf(-z1));
                    float s2 = __fdividef(1.f, 1.f + __expf(-z2));
                    float s3 = __fdividef(1.f, 1.f + __expf(-z3));
                    oac[mi][nj][0] = fmaf(l0, s0, oac[mi][nj][0]);
                    oac[mi][nj][1] = fmaf(l0, s1, oac[mi][nj][1]);
                    oac[mi][nj][2] = fmaf(l1, s2, oac[mi][nj][2]);
                    oac[mi][nj][3] = fmaf(l1, s3, oac[mi][nj][3]);
                    acc[mi][nj][0] = 0.f; acc[mi][nj][1] = 0.f;
                    acc[mi][nj][2] = 0.f; acc[mi][nj][3] = 0.f;
                }
            }
        }
    }

    // ---- final store: out tile [128 x 128] fp32 ----
#pragma unroll
    for (int mi = 0; mi < 4; mi++) {
        const int r0g = st * 128 + wm * 64 + mi * 16 + rowL;
#pragma unroll
        for (int nj = 0; nj < 4; nj++) {
            const int col = ot * 128 + wn * 32 + nj * 8 + colL;
            *reinterpret_cast<float2*>(out + (size_t)r0g * 512 + col) =
                make_float2(oac[mi][nj][0], oac[mi][nj][1]);
            *reinterpret_cast<float2*>(out + (size_t)(r0g + 8) * 512 + col) =
                make_float2(oac[mi][nj][2], oac[mi][nj][3]);
        }
    }
}

// ------------------------------- launcher ----------------------------------
extern "C" void kernel_launch(void* const* d_in, const int* in_sizes, int n_in,
                              void* d_out, int out_size) {
    (void)in_sizes; (void)n_in; (void)out_size;
    const float* X   = (const float*)d_in[0];   // [8192,1024]
    const float* W   = (const float*)d_in[1];   // [8192,1024]
    const float* b   = (const float*)d_in[2];   // [8192]
    const float* lam = (const float*)d_in[3];   // [8192,16]
    float* out = (float*)d_out;                 // [8192,512]

    cudaFuncSetAttribute(somfnn_main,
                         cudaFuncAttributeMaxDynamicSharedMemorySize, SMEM_BYTES);

    pack_kernel<<<8192, 256>>>(X, W);
    somfnn_main<<<256, 256, SMEM_BYTES>>>(b, lam, out);
}

// round 8
// speedup vs baseline: 1.0370x; 1.0370x over previous
#include <cuda_runtime.h>
#include <cuda_bf16.h>
#include <cstdint>
#include <cstddef>

// ---------------------------------------------------------------------------
// out[s,o] = sum_r lambda[s,r] * sigmoid( X[s,:] . W[r*512+o,:] + b[r*512+o] )
// S=8192, K=1024, R=16, O=512.
//
// bf16 HMMA (mma.sync.m16n8k16) — compute_103 target has no tcgen05.
// R8: 512 threads / 16 warps (warp tile 32x32), BK=128, 3-stage cp.async
// pipeline (192KB smem), fused per-rule sigmoid+lambda epilogue in registers.
// ---------------------------------------------------------------------------

#define BM 128
#define BN 128
#define BK 128
#define STAGES 3
#define ROWB 256                           // bytes per smem row (BK*2)
#define A_BYTES (BM * ROWB)                // 32768
#define B_BYTES (BN * ROWB)                // 32768
#define STAGE_BYTES (A_BYTES + B_BYTES)    // 65536
#define SMEM_BYTES (STAGES * STAGE_BYTES)  // 196608
#define NITER 128                          // 16 rules * 8 k-chunks

__device__ __align__(16) __nv_bfloat16 gXbf[8388608];   // 8192 x 1024
__device__ __align__(16) __nv_bfloat16 gWbf[8388608];   // 8192 x 1024

// ------------------------------ PTX helpers --------------------------------
static __device__ __forceinline__ uint32_t smem_u32(const void* p) {
    uint32_t a;
    asm("{ .reg .u64 t; cvta.to.shared.u64 t, %1; cvt.u32.u64 %0, t; }"
        : "=r"(a) : "l"(p));
    return a;
}
static __device__ __forceinline__ void cpa16(uint32_t dst, const void* src) {
    asm volatile("cp.async.cg.shared.global [%0], [%1], 16;"
                 :: "r"(dst), "l"(src) : "memory");
}
static __device__ __forceinline__ void cp_commit() {
    asm volatile("cp.async.commit_group;" ::: "memory");
}
template <int N> static __device__ __forceinline__ void cp_wait() {
    asm volatile("cp.async.wait_group %0;" :: "n"(N) : "memory");
}
static __device__ __forceinline__ void ldsm4(uint32_t& r0, uint32_t& r1,
                                             uint32_t& r2, uint32_t& r3,
                                             uint32_t addr) {
    asm volatile("ldmatrix.sync.aligned.m8n8.x4.shared.b16 {%0,%1,%2,%3}, [%4];"
                 : "=r"(r0), "=r"(r1), "=r"(r2), "=r"(r3) : "r"(addr));
}
static __device__ __forceinline__ void mma16816(
    float& c0, float& c1, float& c2, float& c3,
    uint32_t a0, uint32_t a1, uint32_t a2, uint32_t a3,
    uint32_t b0, uint32_t b1) {
    asm volatile(
        "mma.sync.aligned.m16n8k16.row.col.f32.bf16.bf16.f32 "
        "{%0,%1,%2,%3}, {%4,%5,%6,%7}, {%8,%9}, {%0,%1,%2,%3};"
        : "+f"(c0), "+f"(c1), "+f"(c2), "+f"(c3)
        : "r"(a0), "r"(a1), "r"(a2), "r"(a3), "r"(b0), "r"(b1));
}

// --------------------------- fp32 -> bf16 pack -----------------------------
__global__ void pack_kernel(const float* __restrict__ X,
                            const float* __restrict__ W) {
    unsigned q = blockIdx.x * blockDim.x + threadIdx.x;  // 2^21 threads exactly
    const float4* src;
    uint4* dst;
    if (q < (1u << 20)) {
        src = reinterpret_cast<const float4*>(X) + (size_t)q * 2;
        dst = reinterpret_cast<uint4*>(gXbf) + q;
    } else {
        unsigned p = q - (1u << 20);
        src = reinterpret_cast<const float4*>(W) + (size_t)p * 2;
        dst = reinterpret_cast<uint4*>(gWbf) + p;
    }
    float4 v0 = src[0];
    float4 v1 = src[1];
    __nv_bfloat162 b0 = __floats2bfloat162_rn(v0.x, v0.y);
    __nv_bfloat162 b1 = __floats2bfloat162_rn(v0.z, v0.w);
    __nv_bfloat162 b2 = __floats2bfloat162_rn(v1.x, v1.y);
    __nv_bfloat162 b3 = __floats2bfloat162_rn(v1.z, v1.w);
    uint4 o;
    o.x = *reinterpret_cast<unsigned*>(&b0);
    o.y = *reinterpret_cast<unsigned*>(&b1);
    o.z = *reinterpret_cast<unsigned*>(&b2);
    o.w = *reinterpret_cast<unsigned*>(&b3);
    *dst = o;
}

// ------------------------------- main kernel -------------------------------
__global__ void __launch_bounds__(512, 1) somfnn_main(
    const float* __restrict__ bias,      // [8192] = [16 rules x 512]
    const float* __restrict__ lambdas,   // [8192 x 16]
    float* __restrict__ out)             // [8192 x 512]
{
    extern __shared__ __align__(128) unsigned char smem[];
    const uint32_t sb = smem_u32(smem);

    const int tid  = threadIdx.x;
    const int lane = tid & 31;
    const int wid  = tid >> 5;           // 0..15
    const int st   = blockIdx.x >> 2;    // S-tile 0..63
    const int ot   = blockIdx.x & 3;     // O-tile 0..3
    const int wm   = wid >> 2;           // 0..3 -> rows wm*32
    const int wn   = wid & 3;            // 0..3 -> cols wn*32

    // ---- loader mapping: thread t -> row t>>2 (0..127), 4 chunks of 16B ----
    const int ldrow = tid >> 2;
    const int ldc0  = (tid & 3) * 4;                  // chunk base (of 16)
    const uint32_t lswz = (uint32_t)(ldrow & 7);
    const __nv_bfloat16* aG = gXbf + (size_t)(st * 128 + ldrow) * 1024;
    const __nv_bfloat16* bG = gWbf + (size_t)(ot * 128 + ldrow) * 1024;
    const uint32_t aDst = sb + (uint32_t)ldrow * ROWB;
    const uint32_t bDst = sb + A_BYTES + (uint32_t)ldrow * ROWB;

    auto load_stage = [&](int itL, int s) {
        const int rule = itL >> 3;
        const int kt   = itL & 7;
        const __nv_bfloat16* as = aG + kt * 128 + ldc0 * 8;
        const __nv_bfloat16* bs = bG + (size_t)rule * 524288 + kt * 128 + ldc0 * 8;
        const uint32_t ab = aDst + (uint32_t)s * STAGE_BYTES;
        const uint32_t bb = bDst + (uint32_t)s * STAGE_BYTES;
#pragma unroll
        for (int j = 0; j < 4; j++) {
            const uint32_t off = (((uint32_t)(ldc0 + j) ^ lswz) * 16u);
            cpa16(ab + off, as + j * 8);
            cpa16(bb + off, bs + j * 8);
        }
    };

    // ---- ldmatrix per-lane invariants ----
    const int laneLo = lane & 15;
    const int laneHi = lane >> 4;
    // A (mi, ks): row = wm*32 + mi*16 + laneLo, chunk = ks*2 + laneHi
    const uint32_t aRow = (uint32_t)(wm * 32 + laneLo);
    const uint32_t aOff = aRow * ROWB;
    const uint32_t sA   = aRow & 7;
    // B x4 (ks): row = wn*32 + nh*16 + (lane>>4)*8 + (lane&7),
    //            chunk = ks*2 + ((lane>>3)&1)
    const uint32_t bRow = (uint32_t)(wn * 32 + ((lane >> 4) << 3) + (lane & 7));
    const uint32_t bOff = bRow * ROWB;
    const uint32_t sB   = bRow & 7;
    const uint32_t bCLo = (uint32_t)((lane >> 3) & 1);

    float acc[2][4][4];   // current-rule MMA accumulators (warp tile 32x32)
    float oac[2][4][4];   // lambda-weighted output accumulators
#pragma unroll
    for (int mi = 0; mi < 2; mi++)
#pragma unroll
        for (int nj = 0; nj < 4; nj++)
#pragma unroll
            for (int q = 0; q < 4; q++) { acc[mi][nj][q] = 0.f; oac[mi][nj][q] = 0.f; }

    const int rowL = lane >> 2;         // 0..7
    const int colL = 2 * (lane & 3);    // 0,2,4,6

    // ---- prologue: fill 2 stages ----
    load_stage(0, 0); cp_commit();
    load_stage(1, 1); cp_commit();

    int cs = 0;                          // compute stage ring index
    int ls = 2;                          // load stage ring index
#pragma unroll 1
    for (int it = 0; it < NITER; it++) {
        __syncthreads();                 // all warps done reading buffer ls
        if (it + 2 < NITER) load_stage(it + 2, ls);
        cp_commit();
        cp_wait<2>();                    // stage `cs` data arrived (this thread)
        __syncthreads();                 // ... and visible to all warps

        const uint32_t As = sb + (uint32_t)cs * STAGE_BYTES;
        const uint32_t Bs = As + A_BYTES;

#pragma unroll
        for (int ks = 0; ks < 8; ks++) {
            uint32_t a[2][4];
#pragma unroll
            for (int mi = 0; mi < 2; mi++) {
                const uint32_t addr = As + aOff + (uint32_t)(mi * 16 * ROWB)
                                    + (((uint32_t)(ks * 2 + laneHi) ^ sA) * 16u);
                ldsm4(a[mi][0], a[mi][1], a[mi][2], a[mi][3], addr);
            }
            uint32_t b[4][2];
#pragma unroll
            for (int nh = 0; nh < 2; nh++) {
                const uint32_t addr = Bs + bOff + (uint32_t)(nh * 16 * ROWB)
                                    + ((((uint32_t)(ks * 2) + bCLo) ^ sB) * 16u);
                uint32_t r0, r1, r2, r3;
                ldsm4(r0, r1, r2, r3, addr);
                b[nh * 2][0] = r0;     b[nh * 2][1] = r1;
                b[nh * 2 + 1][0] = r2; b[nh * 2 + 1][1] = r3;
            }
#pragma unroll
            for (int mi = 0; mi < 2; mi++)
#pragma unroll
                for (int nj = 0; nj < 4; nj++)
                    mma16816(acc[mi][nj][0], acc[mi][nj][1],
                             acc[mi][nj][2], acc[mi][nj][3],
                             a[mi][0], a[mi][1], a[mi][2], a[mi][3],
                             b[nj][0], b[nj][1]);
        }

        // ---- per-rule epilogue: sigmoid + lambda-weighted accumulate ----
        if ((it & 7) == 7) {
            const int r = it >> 3;
#pragma unroll
            for (int mi = 0; mi < 2; mi++) {
                const int r0g = st * 128 + wm * 32 + mi * 16 + rowL;
                const float l0 = __ldg(lambdas + (size_t)r0g * 16 + r);
                const float l1 = __ldg(lambdas + (size_t)(r0g + 8) * 16 + r);
#pragma unroll
                for (int nj = 0; nj < 4; nj++) {
                    const int col = ot * 128 + wn * 32 + nj * 8 + colL;
                    const float2 bb = *reinterpret_cast<const float2*>(
                        bias + r * 512 + col);
                    float z0 = acc[mi][nj][0] + bb.x;
                    float z1 = acc[mi][nj][1] + bb.y;
                    float z2 = acc[mi][nj][2] + bb.x;
                    float z3 = acc[mi][nj][3] + bb.y;
                    float s0 = __fdividef(1.f, 1.f + __expf(-z0));
                    float s1 = __fdividef(1.f, 1.f + __expf(-z1));
                    float s2 = __fdividef(1.f, 1.f + __expf(-z2));
                    float s3 = __fdividef(1.f, 1.f + __expf(-z3));
                    oac[mi][nj][0] = fmaf(l0, s0, oac[mi][nj][0]);
                    oac[mi][nj][1] = fmaf(l0, s1, oac[mi][nj][1]);
                    oac[mi][nj][2] = fmaf(l1, s2, oac[mi][nj][2]);
                    oac[mi][nj][3] = fmaf(l1, s3, oac[mi][nj][3]);
                    acc[mi][nj][0] = 0.f; acc[mi][nj][1] = 0.f;
                    acc[mi][nj][2] = 0.f; acc[mi][nj][3] = 0.f;
                }
            }
        }

        cs = (cs == STAGES - 1) ? 0 : cs + 1;
        ls = (ls == STAGES - 1) ? 0 : ls + 1;
    }

    // ---- final store: out tile [128 x 128] fp32 ----
#pragma unroll
    for (int mi = 0; mi < 2; mi++) {
        const int r0g = st * 128 + wm * 32 + mi * 16 + rowL;
#pragma unroll
        for (int nj = 0; nj < 4; nj++) {
            const int col = ot * 128 + wn * 32 + nj * 8 + colL;
            *reinterpret_cast<float2*>(out + (size_t)r0g * 512 + col) =
                make_float2(oac[mi][nj][0], oac[mi][nj][1]);
            *reinterpret_cast<float2*>(out + (size_t)(r0g + 8) * 512 + col) =
                make_float2(oac[mi][nj][2], oac[mi][nj][3]);
        }
    }
}

// ------------------------------- launcher ----------------------------------
extern "C" void kernel_launch(void* const* d_in, const int* in_sizes, int n_in,
                              void* d_out, int out_size) {
    (void)in_sizes; (void)n_in; (void)out_size;
    const float* X   = (const float*)d_in[0];   // [8192,1024]
    const float* W   = (const float*)d_in[1];   // [8192,1024]
    const float* b   = (const float*)d_in[2];   // [8192]
    const float* lam = (const float*)d_in[3];   // [8192,16]
    float* out = (float*)d_out;                 // [8192,512]

    cudaFuncSetAttribute(somfnn_main,
                         cudaFuncAttributeMaxDynamicSharedMemorySize, SMEM_BYTES);

    pack_kernel<<<8192, 256>>>(X, W);
    somfnn_main<<<256, 512, SMEM_BYTES>>>(b, lam, out);
}

// round 9
// speedup vs baseline: 1.0929x; 1.0539x over previous
#include <cuda_runtime.h>
#include <cuda_bf16.h>
#include <cstdint>
#include <cstddef>

// ---------------------------------------------------------------------------
// out[s,o] = sum_r lambda[s,r] * sigmoid( X[s,:] . W[r*512+o,:] + b[r*512+o] )
// S=8192, K=1024, R=16, O=512.
//
// bf16 HMMA (mma.sync.m16n8k16). R9: 2 CTAs/SM for stall overlap.
//   CTA: 256 thr / 8 warps, tile 128x64 (warps 4x2 of 32x32), BK=64,
//   3-stage cp.async pipeline (72KB smem), ONE __syncthreads per iter,
//   fused per-rule sigmoid+lambda epilogue in registers.
//   Grid 512 = 64 S-tiles x 8 O-tiles.
// ---------------------------------------------------------------------------

#define BM 128
#define BN 64
#define BK 64
#define STAGES 3
#define ROWB 128                           // bytes per smem row (BK*2)
#define A_BYTES (BM * ROWB)                // 16384
#define B_BYTES (BN * ROWB)                // 8192
#define STAGE_BYTES (A_BYTES + B_BYTES)    // 24576
#define SMEM_BYTES (STAGES * STAGE_BYTES)  // 73728
#define NITER 256                          // 16 rules * 16 k-chunks

__device__ __align__(16) __nv_bfloat16 gXbf[8388608];   // 8192 x 1024
__device__ __align__(16) __nv_bfloat16 gWbf[8388608];   // 8192 x 1024

// ------------------------------ PTX helpers --------------------------------
static __device__ __forceinline__ uint32_t smem_u32(const void* p) {
    uint32_t a;
    asm("{ .reg .u64 t; cvta.to.shared.u64 t, %1; cvt.u32.u64 %0, t; }"
        : "=r"(a) : "l"(p));
    return a;
}
static __device__ __forceinline__ void cpa16(uint32_t dst, const void* src) {
    asm volatile("cp.async.cg.shared.global [%0], [%1], 16;"
                 :: "r"(dst), "l"(src) : "memory");
}
static __device__ __forceinline__ void cp_commit() {
    asm volatile("cp.async.commit_group;" ::: "memory");
}
template <int N> static __device__ __forceinline__ void cp_wait() {
    asm volatile("cp.async.wait_group %0;" :: "n"(N) : "memory");
}
static __device__ __forceinline__ void ldsm4(uint32_t& r0, uint32_t& r1,
                                             uint32_t& r2, uint32_t& r3,
                                             uint32_t addr) {
    asm volatile("ldmatrix.sync.aligned.m8n8.x4.shared.b16 {%0,%1,%2,%3}, [%4];"
                 : "=r"(r0), "=r"(r1), "=r"(r2), "=r"(r3) : "r"(addr));
}
static __device__ __forceinline__ void mma16816(
    float& c0, float& c1, float& c2, float& c3,
    uint32_t a0, uint32_t a1, uint32_t a2, uint32_t a3,
    uint32_t b0, uint32_t b1) {
    asm volatile(
        "mma.sync.aligned.m16n8k16.row.col.f32.bf16.bf16.f32 "
        "{%0,%1,%2,%3}, {%4,%5,%6,%7}, {%8,%9}, {%0,%1,%2,%3};"
        : "+f"(c0), "+f"(c1), "+f"(c2), "+f"(c3)
        : "r"(a0), "r"(a1), "r"(a2), "r"(a3), "r"(b0), "r"(b1));
}

// --------------------------- fp32 -> bf16 pack -----------------------------
__global__ void pack_kernel(const float* __restrict__ X,
                            const float* __restrict__ W) {
    unsigned q = blockIdx.x * blockDim.x + threadIdx.x;  // 2^21 threads exactly
    const float4* src;
    uint4* dst;
    if (q < (1u << 20)) {
        src = reinterpret_cast<const float4*>(X) + (size_t)q * 2;
        dst = reinterpret_cast<uint4*>(gXbf) + q;
    } else {
        unsigned p = q - (1u << 20);
        src = reinterpret_cast<const float4*>(W) + (size_t)p * 2;
        dst = reinterpret_cast<uint4*>(gWbf) + p;
    }
    float4 v0 = src[0];
    float4 v1 = src[1];
    __nv_bfloat162 b0 = __floats2bfloat162_rn(v0.x, v0.y);
    __nv_bfloat162 b1 = __floats2bfloat162_rn(v0.z, v0.w);
    __nv_bfloat162 b2 = __floats2bfloat162_rn(v1.x, v1.y);
    __nv_bfloat162 b3 = __floats2bfloat162_rn(v1.z, v1.w);
    uint4 o;
    o.x = *reinterpret_cast<unsigned*>(&b0);
    o.y = *reinterpret_cast<unsigned*>(&b1);
    o.z = *reinterpret_cast<unsigned*>(&b2);
    o.w = *reinterpret_cast<unsigned*>(&b3);
    *dst = o;
}

// ------------------------------- main kernel -------------------------------
__global__ void __launch_bounds__(256, 2) somfnn_main(
    const float* __restrict__ bias,      // [8192] = [16 rules x 512]
    const float* __restrict__ lambdas,   // [8192 x 16]
    float* __restrict__ out)             // [8192 x 512]
{
    extern __shared__ __align__(128) unsigned char smem[];
    const uint32_t sb = smem_u32(smem);

    const int tid  = threadIdx.x;
    const int lane = tid & 31;
    const int wid  = tid >> 5;           // 0..7
    const int st   = blockIdx.x >> 3;    // S-tile 0..63
    const int ot   = blockIdx.x & 7;     // O-tile 0..7
    const int wm   = wid >> 1;           // 0..3 -> rows wm*32
    const int wn   = wid & 1;            // 0..1 -> cols wn*32

    // ---- loader mapping ----
    // A: 128 rows x 8 chunks(16B) = 1024 chunks; thread t -> row t>>1, 4 chunks
    // B:  64 rows x 8 chunks      =  512 chunks; thread t -> row t>>2, 2 chunks
    const int arow = tid >> 1;
    const int ac0  = (tid & 1) * 4;
    const int brow = tid >> 2;
    const int bc0  = (tid & 3) * 2;
    const uint32_t aswz = (uint32_t)(arow & 7);
    const uint32_t bswz = (uint32_t)(brow & 7);
    const __nv_bfloat16* aG = gXbf + (size_t)(st * 128 + arow) * 1024;
    const __nv_bfloat16* bG = gWbf + (size_t)(ot * 64 + brow) * 1024;
    const uint32_t aDst = sb + (uint32_t)arow * ROWB;
    const uint32_t bDst = sb + A_BYTES + (uint32_t)brow * ROWB;

    auto load_stage = [&](int itL, int s) {
        const int rule = itL >> 4;
        const int kt   = itL & 15;
        const __nv_bfloat16* as = aG + kt * 64 + ac0 * 8;
        const __nv_bfloat16* bs = bG + (size_t)rule * 524288 + kt * 64 + bc0 * 8;
        const uint32_t ab = aDst + (uint32_t)s * STAGE_BYTES;
        const uint32_t bb = bDst + (uint32_t)s * STAGE_BYTES;
#pragma unroll
        for (int j = 0; j < 4; j++)
            cpa16(ab + (((uint32_t)(ac0 + j) ^ aswz) * 16u), as + j * 8);
#pragma unroll
        for (int j = 0; j < 2; j++)
            cpa16(bb + (((uint32_t)(bc0 + j) ^ bswz) * 16u), bs + j * 8);
    };

    // ---- ldmatrix per-lane invariants (ROWB = 128, chunks 0..7) ----
    const int laneLo = lane & 15;
    const int laneHi = lane >> 4;
    const uint32_t aRow = (uint32_t)(wm * 32 + laneLo);
    const uint32_t aOff = aRow * ROWB;
    const uint32_t sA   = aRow & 7;
    const uint32_t bRow = (uint32_t)(wn * 32 + ((lane >> 4) << 3) + (lane & 7));
    const uint32_t bOff = bRow * ROWB;
    const uint32_t sB   = bRow & 7;
    const uint32_t bCLo = (uint32_t)((lane >> 3) & 1);

    float acc[2][4][4];
    float oac[2][4][4];
#pragma unroll
    for (int mi = 0; mi < 2; mi++)
#pragma unroll
        for (int nj = 0; nj < 4; nj++)
#pragma unroll
            for (int q = 0; q < 4; q++) { acc[mi][nj][q] = 0.f; oac[mi][nj][q] = 0.f; }

    const int rowL = lane >> 2;
    const int colL = 2 * (lane & 3);

    // ---- prologue: fill stages 0 and 1 ----
    load_stage(0, 0); cp_commit();
    load_stage(1, 1); cp_commit();

    int cs = 0;    // compute slot
    int ls = 2;    // load slot (for it+2)
#pragma unroll 1
    for (int it = 0; it < NITER; it++) {
        cp_wait<1>();                    // group `it` complete (≤1 in flight)
        __syncthreads();                 // visible to all; slot ls fully read
        if (it + 2 < NITER) load_stage(it + 2, ls);
        cp_commit();

        const uint32_t As = sb + (uint32_t)cs * STAGE_BYTES;
        const uint32_t Bs = As + A_BYTES;

#pragma unroll
        for (int ks = 0; ks < 4; ks++) {
            uint32_t a[2][4];
#pragma unroll
            for (int mi = 0; mi < 2; mi++) {
                const uint32_t addr = As + aOff + (uint32_t)(mi * 16 * ROWB)
                                    + (((uint32_t)(ks * 2 + laneHi) ^ sA) * 16u);
                ldsm4(a[mi][0], a[mi][1], a[mi][2], a[mi][3], addr);
            }
            uint32_t b[4][2];
#pragma unroll
            for (int nh = 0; nh < 2; nh++) {
                const uint32_t addr = Bs + bOff + (uint32_t)(nh * 16 * ROWB)
                                    + ((((uint32_t)(ks * 2) + bCLo) ^ sB) * 16u);
                uint32_t r0, r1, r2, r3;
                ldsm4(r0, r1, r2, r3, addr);
                b[nh * 2][0] = r0;     b[nh * 2][1] = r1;
                b[nh * 2 + 1][0] = r2; b[nh * 2 + 1][1] = r3;
            }
#pragma unroll
            for (int mi = 0; mi < 2; mi++)
#pragma unroll
                for (int nj = 0; nj < 4; nj++)
                    mma16816(acc[mi][nj][0], acc[mi][nj][1],
                             acc[mi][nj][2], acc[mi][nj][3],
                             a[mi][0], a[mi][1], a[mi][2], a[mi][3],
                             b[nj][0], b[nj][1]);
        }

        // ---- per-rule epilogue ----
        if ((it & 15) == 15) {
            const int r = it >> 4;
#pragma unroll
            for (int mi = 0; mi < 2; mi++) {
                const int r0g = st * 128 + wm * 32 + mi * 16 + rowL;
                const float l0 = __ldg(lambdas + (size_t)r0g * 16 + r);
                const float l1 = __ldg(lambdas + (size_t)(r0g + 8) * 16 + r);
#pragma unroll
                for (int nj = 0; nj < 4; nj++) {
                    const int col = ot * 64 + wn * 32 + nj * 8 + colL;
                    const float2 bb = *reinterpret_cast<const float2*>(
                        bias + r * 512 + col);
                    float z0 = acc[mi][nj][0] + bb.x;
                    float z1 = acc[mi][nj][1] + bb.y;
                    float z2 = acc[mi][nj][2] + bb.x;
                    float z3 = acc[mi][nj][3] + bb.y;
                    float s0 = __fdividef(1.f, 1.f + __expf(-z0));
                    float s1 = __fdividef(1.f, 1.f + __expf(-z1));
                    float s2 = __fdividef(1.f, 1.f + __expf(-z2));
                    float s3 = __fdividef(1.f, 1.f + __expf(-z3));
                    oac[mi][nj][0] = fmaf(l0, s0, oac[mi][nj][0]);
                    oac[mi][nj][1] = fmaf(l0, s1, oac[mi][nj][1]);
                    oac[mi][nj][2] = fmaf(l1, s2, oac[mi][nj][2]);
                    oac[mi][nj][3] = fmaf(l1, s3, oac[mi][nj][3]);
                    acc[mi][nj][0] = 0.f; acc[mi][nj][1] = 0.f;
                    acc[mi][nj][2] = 0.f; acc[mi][nj][3] = 0.f;
                }
            }
        }

        cs = (cs == STAGES - 1) ? 0 : cs + 1;
        ls = (ls == STAGES - 1) ? 0 : ls + 1;
    }

    // ---- final store: out tile [128 x 64] fp32 ----
#pragma unroll
    for (int mi = 0; mi < 2; mi++) {
        const int r0g = st * 128 + wm * 32 + mi * 16 + rowL;
#pragma unroll
        for (int nj = 0; nj < 4; nj++) {
            const int col = ot * 64 + wn * 32 + nj * 8 + colL;
            *reinterpret_cast<float2*>(out + (size_t)r0g * 512 + col) =
                make_float2(oac[mi][nj][0], oac[mi][nj][1]);
            *reinterpret_cast<float2*>(out + (size_t)(r0g + 8) * 512 + col) =
                make_float2(oac[mi][nj][2], oac[mi][nj][3]);
        }
    }
}

// ------------------------------- launcher ----------------------------------
extern "C" void kernel_launch(void* const* d_in, const int* in_sizes, int n_in,
                              void* d_out, int out_size) {
    (void)in_sizes; (void)n_in; (void)out_size;
    const float* X   = (const float*)d_in[0];   // [8192,1024]
    const float* W   = (const float*)d_in[1];   // [8192,1024]
    const float* b   = (const float*)d_in[2];   // [8192]
    const float* lam = (const float*)d_in[3];   // [8192,16]
    float* out = (float*)d_out;                 // [8192,512]

    cudaFuncSetAttribute(somfnn_main,
                         cudaFuncAttributeMaxDynamicSharedMemorySize, SMEM_BYTES);

    pack_kernel<<<8192, 256>>>(X, W);
    somfnn_main<<<512, 256, SMEM_BYTES>>>(b, lam, out);
}